// round 15
// baseline (speedup 1.0000x reference)
#include <cuda_runtime.h>
#include <cuda_bf16.h>
#include <cstdint>

#define DEV __device__ __forceinline__
DEV float sigm(float x){ return 1.0f/(1.0f+__expf(-x)); }
DEV float ftanh(float x){ return 1.0f - 2.0f/(__expf(2.0f*x)+1.0f); }
DEV float tanha(float x){ float r; asm("tanh.approx.f32 %0, %1;" : "=f"(r) : "f"(x)); return r; }
DEV unsigned swz(unsigned off){ return off ^ ((off>>3)&0x70); }

// dims: B=64,S=50,T=50,U=1024,E=256,VT=16000,G3=3072
constexpr long O_ENCGI = 0;                      // 3200x3072 row=t*64+b
constexpr long O_DEMB  = O_ENCGI + 9830400L;     // 3136x3072 row=t*64+b
constexpr long O_PART  = O_DEMB  + 9633792L;     // 4 x 64x3072 split-K partials
constexpr long O_QPART = O_PART  + 786432L;      // 4 x 64x1024
constexpr long O_HF    = O_QPART + 262144L;      // 64x1024 f32 enc h
constexpr long O_NLL   = O_HF    + 65536L;       // 3136
constexpr long SCRATCH_TOTAL = O_NLL + 3200L;

__device__ __align__(16) float g_scratch[SCRATCH_TOTAL];
__device__ int g_didx[3136];
__device__ int g_eidx[3200];

__device__ __align__(16) __nv_bfloat16 g_fcWb[16384000];
__device__ __align__(16) __nv_bfloat16 g_encWhb[3145728];
__device__ __align__(16) __nv_bfloat16 g_W1b[1048576];
__device__ __align__(16) __nv_bfloat16 g_decWxb[3145728];
__device__ __align__(16) __nv_bfloat16 g_decWxb2[786432];
__device__ __align__(16) __nv_bfloat16 g_encWxb[786432];
__device__ __align__(16) __nv_bfloat16 g_W2b[1048576];
__device__ __align__(16) __nv_bfloat16 g_encEmbb[3072000];
__device__ __align__(16) __nv_bfloat16 g_decEmbb[4096000];
__device__ __align__(16) __nv_bfloat16 g_hb[65536];       // recurrent state
__device__ __align__(16) __nv_bfloat16 g_ctxb[65536];
__device__ __align__(16) __nv_bfloat16 g_eob[3276800];    // row=b*50+t
__device__ __align__(16) __nv_bfloat16 g_keysb[3276800];  // row=b*50+t
__device__ __align__(16) __nv_bfloat16 g_hallb[3211264];  // row=t*64+b
__device__ __align__(16) __nv_bfloat16 g_logitsb[50176000];

__global__ void setup_all(const int* __restrict__ inp, const int* __restrict__ targ,
                          const float* __restrict__ hsrc, float* __restrict__ hf,
                          __nv_bfloat16* __restrict__ hb){
    int i = blockIdx.x*256 + threadIdx.x;
    if (i < 65536){ float v = hsrc[i]; hf[i] = v; hb[i] = __float2bfloat16(v); }
    if (i < 3136){ int t = i >> 6, b = i & 63; g_didx[i] = targ[b*50 + t]; }
    if (i < 3200){ int t = i >> 6, b = i & 63; g_eidx[i] = inp[b*50 + t]; }
}

// ---- single merged bf16 conversion over 9 segments ----
constexpr long C1=16384000L, C2=19529728L, C3=20578304L, C4=23724032L, C5=24510464L,
               C6=25296896L, C7=26345472L, C8=29417472L, C9=33513472L;
__global__ void cvt_all(
    const float* s0, __nv_bfloat16* d0, const float* s1, __nv_bfloat16* d1,
    const float* s2, __nv_bfloat16* d2, const float* s3, __nv_bfloat16* d3,
    const float* s4, __nv_bfloat16* d4, const float* s5, __nv_bfloat16* d5,
    const float* s6, __nv_bfloat16* d6, const float* s7, __nv_bfloat16* d7,
    const float* s8, __nv_bfloat16* d8)
{
    long i = ((long)blockIdx.x*256 + threadIdx.x)*4;
    const float* src; __nv_bfloat16* dst; long off;
    if      (i < C1){ src=s0; dst=d0; off=i; }
    else if (i < C2){ src=s1; dst=d1; off=i-C1; }
    else if (i < C3){ src=s2; dst=d2; off=i-C2; }
    else if (i < C4){ src=s3; dst=d3; off=i-C3; }
    else if (i < C5){ src=s4; dst=d4; off=i-C4; }
    else if (i < C6){ src=s5; dst=d5; off=i-C5; }
    else if (i < C7){ src=s6; dst=d6; off=i-C6; }
    else if (i < C8){ src=s7; dst=d7; off=i-C7; }
    else if (i < C9){ src=s8; dst=d8; off=i-C8; }
    else return;
    float4 v = *reinterpret_cast<const float4*>(src + off);
    __nv_bfloat162 lo = __floats2bfloat162_rn(v.x, v.y);
    __nv_bfloat162 hi = __floats2bfloat162_rn(v.z, v.w);
    uint2 o; o.x = *reinterpret_cast<unsigned*>(&lo); o.y = *reinterpret_cast<unsigned*>(&hi);
    *reinterpret_cast<uint2*>(dst + off) = o;
}

// ---- general 64x64 mma GEMM, gather A, f32 and/or bf16 out (R6-proven) ----
__global__ __launch_bounds__(256) void gemm_mma(
    const __nv_bfloat16* __restrict__ A, int lda, const int* __restrict__ gidx,
    const __nv_bfloat16* __restrict__ Bm, int ldb, const float* __restrict__ bias,
    float* __restrict__ C, __nv_bfloat16* __restrict__ Cb, int ldc, int K)
{
    __shared__ __align__(16) char smA[2][8192];
    __shared__ __align__(16) char smB[2][8192];
    const int tid = threadIdx.x, warp = tid >> 5, lane = tid & 31;
    const int wm = warp >> 2, wn = warp & 3;
    const int row0 = blockIdx.y << 6, col0 = blockIdx.x << 6;
    unsigned sA[2] = { (unsigned)__cvta_generic_to_shared(smA[0]), (unsigned)__cvta_generic_to_shared(smA[1]) };
    unsigned sB[2] = { (unsigned)__cvta_generic_to_shared(smB[0]), (unsigned)__cvta_generic_to_shared(smB[1]) };
    float acc[2][2][4] = {};
    const int lr = tid >> 3, lc = tid & 7;
    long ar0 = gidx ? (long)gidx[row0+lr]*lda    : (long)(row0+lr)*lda;
    long ar1 = gidx ? (long)gidx[row0+lr+32]*lda : (long)(row0+lr+32)*lda;
    auto issue = [&](int st, int k0){
        asm volatile("cp.async.cg.shared.global [%0], [%1], 16;"
            :: "r"(sA[st] + swz(lr*128 + lc*16)), "l"(A + ar0 + k0 + lc*8));
        asm volatile("cp.async.cg.shared.global [%0], [%1], 16;"
            :: "r"(sA[st] + swz((lr+32)*128 + lc*16)), "l"(A + ar1 + k0 + lc*8));
        #pragma unroll
        for (int i=0;i<2;i++){
            int r = lr + i*32;
            asm volatile("cp.async.cg.shared.global [%0], [%1], 16;"
                :: "r"(sB[st] + swz(r*128 + lc*16)), "l"(Bm + (long)(k0+r)*ldb + col0 + lc*8));
        }
        asm volatile("cp.async.commit_group;");
    };
    const int nk = K >> 6;
    issue(0, 0);
    for (int kt = 0; kt < nk; kt++){
        if (kt + 1 < nk){ issue((kt+1)&1, (kt+1)<<6); asm volatile("cp.async.wait_group 1;" ::: "memory"); }
        else asm volatile("cp.async.wait_group 0;" ::: "memory");
        __syncthreads();
        const int st = kt & 1;
        #pragma unroll
        for (int ks = 0; ks < 4; ks++){
            unsigned a[2][4];
            #pragma unroll
            for (int mt = 0; mt < 2; mt++){
                int r = wm*32 + mt*16 + (lane & 15), c = ks*16 + (lane >> 4)*8;
                asm volatile("ldmatrix.sync.aligned.m8n8.x4.shared.b16 {%0,%1,%2,%3}, [%4];"
                    : "=r"(a[mt][0]),"=r"(a[mt][1]),"=r"(a[mt][2]),"=r"(a[mt][3])
                    : "r"(sA[st] + swz(r*128 + c*2)));
            }
            unsigned b[4];
            int kk = ks*16 + ((lane>>3)&1)*8 + (lane & 7), nn = wn*16 + (lane>>4)*8;
            asm volatile("ldmatrix.sync.aligned.m8n8.x4.trans.shared.b16 {%0,%1,%2,%3}, [%4];"
                : "=r"(b[0]),"=r"(b[1]),"=r"(b[2]),"=r"(b[3])
                : "r"(sB[st] + swz(kk*128 + nn*2)));
            #pragma unroll
            for (int mt = 0; mt < 2; mt++)
                #pragma unroll
                for (int nt = 0; nt < 2; nt++){
                    float* d = acc[mt][nt];
                    asm volatile("mma.sync.aligned.m16n8k16.row.col.f32.bf16.bf16.f32 "
                        "{%0,%1,%2,%3}, {%4,%5,%6,%7}, {%8,%9}, {%0,%1,%2,%3};"
                        : "+f"(d[0]),"+f"(d[1]),"+f"(d[2]),"+f"(d[3])
                        : "r"(a[mt][0]),"r"(a[mt][1]),"r"(a[mt][2]),"r"(a[mt][3]),
                          "r"(b[nt*2]),"r"(b[nt*2+1]));
                }
        }
        __syncthreads();
    }
    const int rb = row0 + wm*32 + (lane>>2), cb = col0 + wn*16 + (lane&3)*2;
    #pragma unroll
    for (int nt = 0; nt < 2; nt++){
        int cc = cb + nt*8;
        float bv0 = bias ? bias[cc] : 0.f, bv1 = bias ? bias[cc+1] : 0.f;
        #pragma unroll
        for (int mt = 0; mt < 2; mt++){
            int r = rb + mt*16;
            float x0 = acc[mt][nt][0]+bv0, x1 = acc[mt][nt][1]+bv1;
            float y0 = acc[mt][nt][2]+bv0, y1 = acc[mt][nt][3]+bv1;
            if (C){
                *reinterpret_cast<float2*>(&C[(long)r*ldc + cc]) = make_float2(x0, x1);
                *reinterpret_cast<float2*>(&C[(long)(r+8)*ldc + cc]) = make_float2(y0, y1);
            }
            if (Cb){
                *reinterpret_cast<__nv_bfloat162*>(&Cb[(long)r*ldc + cc]) = __floats2bfloat162_rn(x0, x1);
                *reinterpret_cast<__nv_bfloat162*>(&Cb[(long)(r+8)*ldc + cc]) = __floats2bfloat162_rn(y0, y1);
            }
        }
    }
}

// ---- split-K skinny GEMM: M=64 fixed, grid (N/64, KS); partial z -> C + z*64*N ----
__global__ __launch_bounds__(256) void gemm_splitk(
    const __nv_bfloat16* __restrict__ A, int lda,
    const __nv_bfloat16* __restrict__ Bm, int ldb,
    float* __restrict__ C, int N, int K, int KS)
{
    __shared__ __align__(16) char smA[2][8192];
    __shared__ __align__(16) char smB[2][8192];
    const int tid = threadIdx.x, warp = tid >> 5, lane = tid & 31;
    const int wm = warp >> 2, wn = warp & 3;
    const int col0 = blockIdx.x << 6;
    const int kbeg = blockIdx.y * (K / KS);
    unsigned sA[2] = { (unsigned)__cvta_generic_to_shared(smA[0]), (unsigned)__cvta_generic_to_shared(smA[1]) };
    unsigned sB[2] = { (unsigned)__cvta_generic_to_shared(smB[0]), (unsigned)__cvta_generic_to_shared(smB[1]) };
    float acc[2][2][4] = {};
    const int lr = tid >> 3, lc = tid & 7;
    auto issue = [&](int st, int k0){
        asm volatile("cp.async.cg.shared.global [%0], [%1], 16;"
            :: "r"(sA[st] + swz(lr*128 + lc*16)), "l"(A + (long)lr*lda + kbeg + k0 + lc*8));
        asm volatile("cp.async.cg.shared.global [%0], [%1], 16;"
            :: "r"(sA[st] + swz((lr+32)*128 + lc*16)), "l"(A + (long)(lr+32)*lda + kbeg + k0 + lc*8));
        #pragma unroll
        for (int i=0;i<2;i++){
            int r = lr + i*32;
            asm volatile("cp.async.cg.shared.global [%0], [%1], 16;"
                :: "r"(sB[st] + swz(r*128 + lc*16)), "l"(Bm + (long)(kbeg+k0+r)*ldb + col0 + lc*8));
        }
        asm volatile("cp.async.commit_group;");
    };
    const int nk = (K / KS) >> 6;
    issue(0, 0);
    for (int kt = 0; kt < nk; kt++){
        if (kt + 1 < nk){ issue((kt+1)&1, (kt+1)<<6); asm volatile("cp.async.wait_group 1;" ::: "memory"); }
        else asm volatile("cp.async.wait_group 0;" ::: "memory");
        __syncthreads();
        const int st = kt & 1;
        #pragma unroll
        for (int ks = 0; ks < 4; ks++){
            unsigned a[2][4];
            #pragma unroll
            for (int mt = 0; mt < 2; mt++){
                int r = wm*32 + mt*16 + (lane & 15), c = ks*16 + (lane >> 4)*8;
                asm volatile("ldmatrix.sync.aligned.m8n8.x4.shared.b16 {%0,%1,%2,%3}, [%4];"
                    : "=r"(a[mt][0]),"=r"(a[mt][1]),"=r"(a[mt][2]),"=r"(a[mt][3])
                    : "r"(sA[st] + swz(r*128 + c*2)));
            }
            unsigned b[4];
            int kk = ks*16 + ((lane>>3)&1)*8 + (lane & 7), nn = wn*16 + (lane>>4)*8;
            asm volatile("ldmatrix.sync.aligned.m8n8.x4.trans.shared.b16 {%0,%1,%2,%3}, [%4];"
                : "=r"(b[0]),"=r"(b[1]),"=r"(b[2]),"=r"(b[3])
                : "r"(sB[st] + swz(kk*128 + nn*2)));
            #pragma unroll
            for (int mt = 0; mt < 2; mt++)
                #pragma unroll
                for (int nt = 0; nt < 2; nt++){
                    float* d = acc[mt][nt];
                    asm volatile("mma.sync.aligned.m16n8k16.row.col.f32.bf16.bf16.f32 "
                        "{%0,%1,%2,%3}, {%4,%5,%6,%7}, {%8,%9}, {%0,%1,%2,%3};"
                        : "+f"(d[0]),"+f"(d[1]),"+f"(d[2]),"+f"(d[3])
                        : "r"(a[mt][0]),"r"(a[mt][1]),"r"(a[mt][2]),"r"(a[mt][3]),
                          "r"(b[nt*2]),"r"(b[nt*2+1]));
                }
        }
        __syncthreads();
    }
    float* Cout = C + (long)blockIdx.y * 64 * N;
    const int rb = wm*32 + (lane>>2), cb = col0 + wn*16 + (lane&3)*2;
    #pragma unroll
    for (int nt = 0; nt < 2; nt++){
        int cc = cb + nt*8;
        #pragma unroll
        for (int mt = 0; mt < 2; mt++){
            int r = rb + mt*16;
            *reinterpret_cast<float2*>(&Cout[(long)r*N + cc]) = make_float2(acc[mt][nt][0], acc[mt][nt][1]);
            *reinterpret_cast<float2*>(&Cout[(long)(r+8)*N + cc]) = make_float2(acc[mt][nt][2], acc[mt][nt][3]);
        }
    }
}

// ---- FUSED decoder q: prologue recomputes h(t-1) slice from gates partials, then q split-K ----
// grid (16,4). smem: [0,32768) A staged (4 x 64x64 chunks), [32768,65536) B (4 chunks of W1).
__global__ __launch_bounds__(256) void dec_q_fused(
    int t, const __nv_bfloat16* __restrict__ hb0,
    const float* __restrict__ part, const float* __restrict__ dembgi,
    const float* __restrict__ decb2, const __nv_bfloat16* __restrict__ W1b,
    float* __restrict__ qpart, __nv_bfloat16* __restrict__ hallb)
{
    extern __shared__ char sm[];
    const int tid = threadIdx.x, warp = tid >> 5, lane = tid & 31;
    const int wm = warp >> 2, wn = warp & 3;
    const int col0 = blockIdx.x << 6, kbeg = blockIdx.y << 8;
    unsigned base = (unsigned)__cvta_generic_to_shared(sm);
    unsigned sA = base, sB = base + 32768;
    const int lr = tid >> 3, lc = tid & 7;

    // prefetch all 4 B (W1) chunks; prologue compute hides the latency
    #pragma unroll
    for (int ch = 0; ch < 4; ch++){
        #pragma unroll
        for (int i = 0; i < 2; i++){
            int r = lr + i*32;
            asm volatile("cp.async.cg.shared.global [%0], [%1], 16;"
                :: "r"(sB + ch*8192 + swz(r*128 + lc*16)),
                   "l"(W1b + (long)(kbeg + ch*64 + r)*1024 + col0 + lc*8));
        }
        asm volatile("cp.async.commit_group;");
    }

    // prologue: build A = h(t-1)[64 x cols kbeg..kbeg+255] in smem (swizzled bf16)
    const int c4 = (tid & 63) << 2;   // col within slice, 4-wide
    const int bo = tid >> 6;          // 0..3
    const int u = kbeg + c4;
    char* adst = sm + (c4 >> 6)*8192;
    const int cb2 = (c4 & 63)*2;
    if (t == 0){
        #pragma unroll
        for (int it = 0; it < 16; it++){
            int b = it*4 + bo;
            uint2 v = *reinterpret_cast<const uint2*>(&hb0[b*1024 + u]);
            *reinterpret_cast<uint2*>(adst + swz(b*128 + cb2)) = v;
        }
    } else {
        const int PS = 196608;
        float4 bz = *reinterpret_cast<const float4*>(&decb2[u]);
        float4 br = *reinterpret_cast<const float4*>(&decb2[1024 + u]);
        float4 bh = *reinterpret_cast<const float4*>(&decb2[2048 + u]);
        const bool wr = (blockIdx.x == 0);
        #pragma unroll 2
        for (int it = 0; it < 16; it++){
            int b = it*4 + bo;
            long p = (long)b*3072 + u;
            long gi = (long)((t-1)*64 + b)*3072 + u;
            float4 m0 = *reinterpret_cast<const float4*>(&part[p]);
            float4 m1 = *reinterpret_cast<const float4*>(&part[PS + p]);
            float4 m2 = *reinterpret_cast<const float4*>(&part[2*PS + p]);
            float4 m3 = *reinterpret_cast<const float4*>(&part[3*PS + p]);
            float4 dz = *reinterpret_cast<const float4*>(&dembgi[gi]);
            float z0 = sigm(dz.x + m0.x + m1.x + m2.x + m3.x + bz.x);
            float z1 = sigm(dz.y + m0.y + m1.y + m2.y + m3.y + bz.y);
            float z2 = sigm(dz.z + m0.z + m1.z + m2.z + m3.z + bz.z);
            float z3 = sigm(dz.w + m0.w + m1.w + m2.w + m3.w + bz.w);
            m0 = *reinterpret_cast<const float4*>(&part[p + 1024]);
            m1 = *reinterpret_cast<const float4*>(&part[PS + p + 1024]);
            m2 = *reinterpret_cast<const float4*>(&part[2*PS + p + 1024]);
            m3 = *reinterpret_cast<const float4*>(&part[3*PS + p + 1024]);
            dz = *reinterpret_cast<const float4*>(&dembgi[gi + 1024]);
            float r0 = sigm(dz.x + m0.x + m1.x + m2.x + m3.x + br.x);
            float r1 = sigm(dz.y + m0.y + m1.y + m2.y + m3.y + br.y);
            float r2 = sigm(dz.z + m0.z + m1.z + m2.z + m3.z + br.z);
            float r3 = sigm(dz.w + m0.w + m1.w + m2.w + m3.w + br.w);
            m0 = *reinterpret_cast<const float4*>(&part[p + 2048]);
            m1 = *reinterpret_cast<const float4*>(&part[PS + p + 2048]);
            m2 = *reinterpret_cast<const float4*>(&part[2*PS + p + 2048]);
            m3 = *reinterpret_cast<const float4*>(&part[3*PS + p + 2048]);
            dz = *reinterpret_cast<const float4*>(&dembgi[gi + 2048]);
            float h0 = (1.0f - z0)*ftanh(dz.x + m0.x + m1.x + m2.x + m3.x + r0*bh.x);
            float h1 = (1.0f - z1)*ftanh(dz.y + m0.y + m1.y + m2.y + m3.y + r1*bh.y);
            float h2 = (1.0f - z2)*ftanh(dz.z + m0.z + m1.z + m2.z + m3.z + r2*bh.z);
            float h3 = (1.0f - z3)*ftanh(dz.w + m0.w + m1.w + m2.w + m3.w + r3*bh.w);
            __nv_bfloat162 lo = __floats2bfloat162_rn(h0, h1);
            __nv_bfloat162 hi = __floats2bfloat162_rn(h2, h3);
            uint2 v; v.x = *reinterpret_cast<unsigned*>(&lo); v.y = *reinterpret_cast<unsigned*>(&hi);
            *reinterpret_cast<uint2*>(adst + swz(b*128 + cb2)) = v;
            if (wr) *reinterpret_cast<uint2*>(&hallb[(long)((t-1)*64 + b)*1024 + u]) = v;
        }
    }
    asm volatile("cp.async.wait_group 0;" ::: "memory");
    __syncthreads();

    float acc[2][2][4] = {};
    #pragma unroll
    for (int kt = 0; kt < 4; kt++){
        unsigned cA = sA + kt*8192, cB = sB + kt*8192;
        #pragma unroll
        for (int ks = 0; ks < 4; ks++){
            unsigned a[2][4];
            #pragma unroll
            for (int mt = 0; mt < 2; mt++){
                int r = wm*32 + mt*16 + (lane & 15), c = ks*16 + (lane >> 4)*8;
                asm volatile("ldmatrix.sync.aligned.m8n8.x4.shared.b16 {%0,%1,%2,%3}, [%4];"
                    : "=r"(a[mt][0]),"=r"(a[mt][1]),"=r"(a[mt][2]),"=r"(a[mt][3])
                    : "r"(cA + swz(r*128 + c*2)));
            }
            unsigned b[4];
            int kk = ks*16 + ((lane>>3)&1)*8 + (lane & 7), nn = wn*16 + (lane>>4)*8;
            asm volatile("ldmatrix.sync.aligned.m8n8.x4.trans.shared.b16 {%0,%1,%2,%3}, [%4];"
                : "=r"(b[0]),"=r"(b[1]),"=r"(b[2]),"=r"(b[3])
                : "r"(cB + swz(kk*128 + nn*2)));
            #pragma unroll
            for (int mt = 0; mt < 2; mt++)
                #pragma unroll
                for (int nt = 0; nt < 2; nt++){
                    float* d = acc[mt][nt];
                    asm volatile("mma.sync.aligned.m16n8k16.row.col.f32.bf16.bf16.f32 "
                        "{%0,%1,%2,%3}, {%4,%5,%6,%7}, {%8,%9}, {%0,%1,%2,%3};"
                        : "+f"(d[0]),"+f"(d[1]),"+f"(d[2]),"+f"(d[3])
                        : "r"(a[mt][0]),"r"(a[mt][1]),"r"(a[mt][2]),"r"(a[mt][3]),
                          "r"(b[nt*2]),"r"(b[nt*2+1]));
                }
        }
    }
    float* Cout = qpart + (long)blockIdx.y * 65536;
    const int rb = wm*32 + (lane>>2), cb = col0 + wn*16 + (lane&3)*2;
    #pragma unroll
    for (int nt = 0; nt < 2; nt++){
        int cc = cb + nt*8;
        #pragma unroll
        for (int mt = 0; mt < 2; mt++){
            int r = rb + mt*16;
            *reinterpret_cast<float2*>(&Cout[(long)r*1024 + cc]) = make_float2(acc[mt][nt][0], acc[mt][nt][1]);
            *reinterpret_cast<float2*>(&Cout[(long)(r+8)*1024 + cc]) = make_float2(acc[mt][nt][2], acc[mt][nt][3]);
        }
    }
}

// ---- encoder GRU combine: sum 4 partials + gates + state update ----
__global__ __launch_bounds__(256) void enc_combine(
    int t, const float* __restrict__ encgi, const float* __restrict__ part,
    const float* __restrict__ encb2,
    float* __restrict__ hf, __nv_bfloat16* __restrict__ hb, __nv_bfloat16* __restrict__ eob)
{
    const int PS = 64*3072;
    int i = blockIdx.x*256 + threadIdx.x;
    int b = i >> 10, u = i & 1023;
    long p = (long)b*3072 + u;
    long gi = (long)(t*64 + b)*3072 + u;
    float ghz = part[p]      + part[PS+p]      + part[2*PS+p]      + part[3*PS+p]      + encb2[u];
    float ghr = part[p+1024] + part[PS+p+1024] + part[2*PS+p+1024] + part[3*PS+p+1024] + encb2[1024+u];
    float ghh = part[p+2048] + part[PS+p+2048] + part[2*PS+p+2048] + part[3*PS+p+2048] + encb2[2048+u];
    float z = sigm(encgi[gi] + ghz);
    float r = sigm(encgi[gi+1024] + ghr);
    float hc = ftanh(encgi[gi+2048] + r*ghh);
    float hn = z*hf[i] + (1.0f - z)*hc;
    hf[i] = hn;
    hb[i] = __float2bfloat16(hn);
    eob[(long)(b*50 + t)*1024 + u] = __float2bfloat16(hn);
}

// ---- decoder GRU combine (h==0) — used only for final step t=48 ----
__global__ __launch_bounds__(256) void dec_combine(
    int t, const float* __restrict__ dembgi, const float* __restrict__ part,
    const float* __restrict__ decb2,
    __nv_bfloat16* __restrict__ hb, __nv_bfloat16* __restrict__ hallb)
{
    const int PS = 64*3072;
    int i = blockIdx.x*256 + threadIdx.x;
    int b = i >> 10, u = i & 1023;
    long p = (long)b*3072 + u;
    long gi = (long)(t*64 + b)*3072 + u;
    float gz = part[p]      + part[PS+p]      + part[2*PS+p]      + part[3*PS+p];
    float gr = part[p+1024] + part[PS+p+1024] + part[2*PS+p+1024] + part[3*PS+p+1024];
    float gh = part[p+2048] + part[PS+p+2048] + part[2*PS+p+2048] + part[3*PS+p+2048];
    float z = sigm(dembgi[gi] + gz + decb2[u]);
    float r = sigm(dembgi[gi+1024] + gr + decb2[1024+u]);
    float hc = ftanh(dembgi[gi+2048] + gh + r*decb2[2048+u]);
    float hn = (1.0f - z)*hc;
    __nv_bfloat16 hv = __float2bfloat16(hn);
    hb[i] = hv;
    hallb[(long)(t*64 + b)*1024 + u] = hv;
}

// ---- fused attention: sum 4 q-partials, scores (tanh.approx), softmax, ctx; bf16 keys/eo ----
__global__ __launch_bounds__(256) void attention(
    const float* __restrict__ qpart, const __nv_bfloat16* __restrict__ keysb,
    const __nv_bfloat16* __restrict__ eob, __nv_bfloat16* __restrict__ ctxb,
    const float* __restrict__ b1, const float* __restrict__ V, const float* __restrict__ bV)
{
    __shared__ float qs[1024];
    __shared__ float Vs[1024];
    __shared__ float sc[64];
    const int b = blockIdx.x, tid = threadIdx.x, warp = tid>>5, lane = tid&31;
    const int QP = 65536;
    for (int u = tid; u < 1024; u += 256){
        long p = b*1024 + u;
        qs[u] = qpart[p] + qpart[QP+p] + qpart[2*QP+p] + qpart[3*QP+p] + b1[u];
        Vs[u] = V[u];
    }
    __syncthreads();
    for (int s = warp; s < 50; s += 8){
        const __nv_bfloat16* kr = keysb + (long)(b*50 + s)*1024;
        float a = 0.f;
        for (int u = lane*2; u < 1024; u += 64){
            __nv_bfloat162 k2 = *reinterpret_cast<const __nv_bfloat162*>(kr + u);
            a += Vs[u]   * tanha(qs[u]   + __bfloat162float(k2.x));
            a += Vs[u+1] * tanha(qs[u+1] + __bfloat162float(k2.y));
        }
        #pragma unroll
        for (int o = 16; o; o >>= 1) a += __shfl_xor_sync(0xffffffffu, a, o);
        if (lane == 0) sc[s] = a + bV[0];
    }
    __syncthreads();
    if (warp == 0){
        float v0 = sc[lane];
        bool has1 = (lane + 32) < 50;
        float v1 = has1 ? sc[lane + 32] : -1e30f;
        float m = fmaxf(v0, v1);
        #pragma unroll
        for (int o = 16; o; o >>= 1) m = fmaxf(m, __shfl_xor_sync(0xffffffffu, m, o));
        float e0 = __expf(v0 - m);
        float e1 = has1 ? __expf(v1 - m) : 0.f;
        float ssum = e0 + e1;
        #pragma unroll
        for (int o = 16; o; o >>= 1) ssum += __shfl_xor_sync(0xffffffffu, ssum, o);
        float inv = 1.0f / ssum;
        sc[lane] = e0 * inv;
        sc[lane + 32] = e1 * inv;
    }
    __syncthreads();
    for (int u0 = tid*2; u0 < 1024; u0 += 512){
        float a0 = 0.f, a1 = 0.f;
        const __nv_bfloat16* er = eob + (long)b*51200 + u0;
        #pragma unroll 10
        for (int s = 0; s < 50; s++){
            __nv_bfloat162 e2 = *reinterpret_cast<const __nv_bfloat162*>(er + (long)s*1024);
            a0 = fmaf(sc[s], __bfloat162float(e2.x), a0);
            a1 = fmaf(sc[s], __bfloat162float(e2.y), a1);
        }
        *reinterpret_cast<__nv_bfloat162*>(&ctxb[b*1024 + u0]) = __floats2bfloat162_rn(a0, a1);
    }
}

// ---- fc GEMM: BM=128 BN=128 BK=64, bf16 out (verified bit-exact) ----
__global__ __launch_bounds__(256) void gemm_fc(
    const __nv_bfloat16* __restrict__ A, const __nv_bfloat16* __restrict__ Bm,
    const float* __restrict__ bias, __nv_bfloat16* __restrict__ Cb)
{
    extern __shared__ char sm[];
    const int tid = threadIdx.x, warp = tid >> 5, lane = tid & 31;
    const int wm = warp >> 2, wn = warp & 3;
    const int row0 = blockIdx.y << 7, col0 = blockIdx.x << 7;
    unsigned base = (unsigned)__cvta_generic_to_shared(sm);
    float acc[4][4][4] = {};
    auto issue = [&](int st, int k0){
        unsigned sA = base + st*32768, sB = sA + 16384;
        int r = tid>>3, c8 = tid&7;
        #pragma unroll
        for (int i=0;i<4;i++){
            int rr = r + i*32;
            int rg = row0 + rr; if (rg > 3135) rg = 3135;
            asm volatile("cp.async.cg.shared.global [%0], [%1], 16;"
                :: "r"(sA + swz(rr*128 + c8*16)), "l"(A + (long)rg*1024 + k0 + c8*8));
        }
        #pragma unroll
        for (int p=0;p<4;p++){
            int idx = p*256 + tid;
            int rr = idx>>4, c16 = idx&15;
            int panel = c16>>3, cp = c16&7;
            asm volatile("cp.async.cg.shared.global [%0], [%1], 16;"
                :: "r"(sB + panel*8192 + swz(rr*128 + cp*16)),
                   "l"(Bm + (long)(k0+rr)*16000 + col0 + c16*8));
        }
        asm volatile("cp.async.commit_group;");
    };
    issue(0, 0);
    for (int kt = 0; kt < 16; kt++){
        if (kt+1 < 16){ issue((kt+1)&1, (kt+1)<<6); asm volatile("cp.async.wait_group 1;" ::: "memory"); }
        else asm volatile("cp.async.wait_group 0;" ::: "memory");
        __syncthreads();
        unsigned sA = base + (kt&1)*32768, sB = sA + 16384;
        #pragma unroll
        for (int ks = 0; ks < 4; ks++){
            unsigned a[4][4];
            #pragma unroll
            for (int mt = 0; mt < 4; mt++){
                int r = wm*64 + mt*16 + (lane & 15), c = ks*16 + (lane >> 4)*8;
                asm volatile("ldmatrix.sync.aligned.m8n8.x4.shared.b16 {%0,%1,%2,%3}, [%4];"
                    : "=r"(a[mt][0]),"=r"(a[mt][1]),"=r"(a[mt][2]),"=r"(a[mt][3])
                    : "r"(sA + swz(r*128 + c*2)));
            }
            #pragma unroll
            for (int nt = 0; nt < 4; nt++){
                int nb = wn*4 + nt;
                int panel = nb>>3, cip = nb&7;
                unsigned b2[2];
                int kk = ks*16 + (lane & 15);
                asm volatile("ldmatrix.sync.aligned.m8n8.x2.trans.shared.b16 {%0,%1}, [%2];"
                    : "=r"(b2[0]),"=r"(b2[1])
                    : "r"(sB + panel*8192 + swz(kk*128 + cip*16)));
                #pragma unroll
                for (int mt = 0; mt < 4; mt++){
                    float* d = acc[mt][nt];
                    asm volatile("mma.sync.aligned.m16n8k16.row.col.f32.bf16.bf16.f32 "
                        "{%0,%1,%2,%3}, {%4,%5,%6,%7}, {%8,%9}, {%0,%1,%2,%3};"
                        : "+f"(d[0]),"+f"(d[1]),"+f"(d[2]),"+f"(d[3])
                        : "r"(a[mt][0]),"r"(a[mt][1]),"r"(a[mt][2]),"r"(a[mt][3]),
                          "r"(b2[0]),"r"(b2[1]));
                }
            }
        }
        __syncthreads();
    }
    #pragma unroll
    for (int nt = 0; nt < 4; nt++){
        int c = col0 + wn*32 + nt*8 + (lane&3)*2;
        float bv0 = bias[c], bv1 = bias[c+1];
        #pragma unroll
        for (int mt = 0; mt < 4; mt++){
            int r = row0 + wm*64 + mt*16 + (lane>>2);
            if (r < 3136)
                *reinterpret_cast<__nv_bfloat162*>(&Cb[(long)r*16000 + c]) =
                    __floats2bfloat162_rn(acc[mt][nt][0]+bv0, acc[mt][nt][1]+bv1);
            if (r+8 < 3136)
                *reinterpret_cast<__nv_bfloat162*>(&Cb[(long)(r+8)*16000 + c]) =
                    __floats2bfloat162_rn(acc[mt][nt][2]+bv0, acc[mt][nt][3]+bv1);
        }
    }
}

// ---- loss over bf16 logits ----
__global__ __launch_bounds__(256) void loss_kernel(
    const __nv_bfloat16* __restrict__ lg, const int* __restrict__ targ, float* __restrict__ nll)
{
    __shared__ float red[256];
    const int row = blockIdx.x, tid = threadIdx.x;
    const int t = row >> 6, b = row & 63;
    const __nv_bfloat16* lr = lg + (long)row*16000;
    float m = -1e30f;
    for (int j = tid*2; j < 16000; j += 512){
        __nv_bfloat162 p = *reinterpret_cast<const __nv_bfloat162*>(lr + j);
        m = fmaxf(m, fmaxf(__bfloat162float(p.x), __bfloat162float(p.y)));
    }
    red[tid] = m; __syncthreads();
    for (int o = 128; o; o >>= 1){ if (tid < o) red[tid] = fmaxf(red[tid], red[tid+o]); __syncthreads(); }
    m = red[0]; __syncthreads();
    float s = 0.f;
    for (int j = tid*2; j < 16000; j += 512){
        __nv_bfloat162 p = *reinterpret_cast<const __nv_bfloat162*>(lr + j);
        s += __expf(__bfloat162float(p.x) - m) + __expf(__bfloat162float(p.y) - m);
    }
    red[tid] = s; __syncthreads();
    for (int o = 128; o; o >>= 1){ if (tid < o) red[tid] += red[tid+o]; __syncthreads(); }
    if (tid == 0){
        int yt = targ[b*50 + t + 1];
        float lse = m + __logf(red[0]);
        nll[row] = (yt != 0) ? (lse - __bfloat162float(lr[yt])) * (1.0f/64.0f) : 0.f;
    }
}
__global__ __launch_bounds__(1024) void final_reduce(const float* __restrict__ nll, float* __restrict__ out){
    __shared__ float red[1024];
    int tid = threadIdx.x;
    float s = 0.f;
    for (int i = tid; i < 3136; i += 1024) s += nll[i];
    red[tid] = s; __syncthreads();
    for (int o = 512; o; o >>= 1){ if (tid < o) red[tid] += red[tid+o]; __syncthreads(); }
    if (tid == 0) out[0] = red[0];
}

extern "C" void kernel_launch(void* const* d_in, const int* in_sizes, int n_in,
                              void* d_out, int out_size) {
    const int*   inp     = (const int*)  d_in[0];
    const int*   targ    = (const int*)  d_in[1];
    const float* enc_hid = (const float*)d_in[2];
    const float* enc_emb = (const float*)d_in[3];
    const float* enc_Wx  = (const float*)d_in[4];
    const float* enc_Wh  = (const float*)d_in[5];
    const float* enc_b   = (const float*)d_in[6];
    const float* W1      = (const float*)d_in[7];
    const float* b1      = (const float*)d_in[8];
    const float* W2      = (const float*)d_in[9];
    const float* b2      = (const float*)d_in[10];
    const float* V       = (const float*)d_in[11];
    const float* bV      = (const float*)d_in[12];
    const float* dec_emb = (const float*)d_in[13];
    const float* dec_Wx  = (const float*)d_in[14];
    const float* dec_b   = (const float*)d_in[16];
    const float* fc_W    = (const float*)d_in[17];
    const float* fc_b    = (const float*)d_in[18];
    float* out = (float*)d_out;

    float* S; cudaGetSymbolAddress((void**)&S, g_scratch);
    int *didx, *eidx;
    cudaGetSymbolAddress((void**)&didx, g_didx);
    cudaGetSymbolAddress((void**)&eidx, g_eidx);
    __nv_bfloat16 *fcWb,*encWhb,*W1b,*decWxb,*decWxb2,*encWxb,*W2b,*encEmbb,*decEmbb;
    __nv_bfloat16 *hb,*ctxb,*eob,*keysb,*hallb,*logitsb;
    cudaGetSymbolAddress((void**)&fcWb,    g_fcWb);
    cudaGetSymbolAddress((void**)&encWhb,  g_encWhb);
    cudaGetSymbolAddress((void**)&W1b,     g_W1b);
    cudaGetSymbolAddress((void**)&decWxb,  g_decWxb);
    cudaGetSymbolAddress((void**)&decWxb2, g_decWxb2);
    cudaGetSymbolAddress((void**)&encWxb,  g_encWxb);
    cudaGetSymbolAddress((void**)&W2b,     g_W2b);
    cudaGetSymbolAddress((void**)&encEmbb, g_encEmbb);
    cudaGetSymbolAddress((void**)&decEmbb, g_decEmbb);
    cudaGetSymbolAddress((void**)&hb,      g_hb);
    cudaGetSymbolAddress((void**)&ctxb,    g_ctxb);
    cudaGetSymbolAddress((void**)&eob,     g_eob);
    cudaGetSymbolAddress((void**)&keysb,   g_keysb);
    cudaGetSymbolAddress((void**)&hallb,   g_hallb);
    cudaGetSymbolAddress((void**)&logitsb, g_logitsb);

    float* encgi = S + O_ENCGI;
    float* dembgi= S + O_DEMB;
    float* part  = S + O_PART;
    float* qpart = S + O_QPART;
    float* hf    = S + O_HF;
    float* nll   = S + O_NLL;

    cudaFuncSetAttribute(gemm_fc,     cudaFuncAttributeMaxDynamicSharedMemorySize, 65536);
    cudaFuncSetAttribute(dec_q_fused, cudaFuncAttributeMaxDynamicSharedMemorySize, 65536);

    setup_all<<<256, 256>>>(inp, targ, enc_hid, hf, hb);

    // all weight/embedding conversions in ONE node
    cvt_all<<<32728, 256>>>(
        fc_W, fcWb, enc_Wh, encWhb, W1, W1b, dec_Wx, decWxb,
        dec_Wx + 1024L*3072, decWxb2, enc_Wx, encWxb, W2, W2b,
        enc_emb, encEmbb, dec_emb, decEmbb);

    // hoisted input-side GEMMs
    gemm_mma<<<dim3(48, 50), 256>>>(encEmbb, 256, eidx, encWxb,  3072, enc_b, encgi,  nullptr, 3072, 256);
    gemm_mma<<<dim3(48, 49), 256>>>(decEmbb, 256, didx, decWxb2, 3072, dec_b, dembgi, nullptr, 3072, 256);

    // encoder: split-K gemm (192 blocks) + combine, per step
    for (int t = 0; t < 50; t++){
        gemm_splitk<<<dim3(48, 4), 256>>>(hb, 1024, encWhb, 3072, part, 3072, 1024, 4);
        enc_combine<<<256, 256>>>(t, encgi, part, enc_b + 3072, hf, hb, eob);
    }

    // keys = enc_out @ W2 + b2 (bf16 out, row = b*50+t)
    gemm_mma<<<dim3(16, 50), 256>>>(eob, 1024, nullptr, W2b, 1024, b2, nullptr, keysb, 1024, 1024);

    // decoder: fused (combine(t-1)+q) + attention + gates split-K  — 3 nodes/step
    for (int t = 0; t < 49; t++){
        dec_q_fused<<<dim3(16, 4), 256, 65536>>>(t, hb, part, dembgi, dec_b + 3072, W1b, qpart, hallb);
        attention<<<64, 256>>>(qpart, keysb, eob, ctxb, b1, V, bV);
        gemm_splitk<<<dim3(48, 4), 256>>>(ctxb, 1024, decWxb, 3072, part, 3072, 1024, 4);
    }
    // final combine produces hallb row t=48
    dec_combine<<<256, 256>>>(48, dembgi, part, dec_b + 3072, hb, hallb);

    // batched fc logits, 128x128 tiles (bf16 out)
    gemm_fc<<<dim3(125, 25), 256, 65536>>>(hallb, fcWb, fc_b, logitsb);

    loss_kernel<<<3136, 256>>>(logitsb, targ, nll);
    final_reduce<<<1, 1024>>>(nll, out);
}

// round 16
// speedup vs baseline: 1.7164x; 1.7164x over previous
#include <cuda_runtime.h>
#include <cuda_bf16.h>
#include <cstdint>

#define DEV __device__ __forceinline__
DEV float sigm(float x){ return 1.0f/(1.0f+__expf(-x)); }
DEV float ftanh(float x){ return 1.0f - 2.0f/(__expf(2.0f*x)+1.0f); }
DEV float tanha(float x){ float r; asm("tanh.approx.f32 %0, %1;" : "=f"(r) : "f"(x)); return r; }
DEV unsigned swz(unsigned off){ return off ^ ((off>>3)&0x70); }

// dims: B=64,S=50,T=50,U=1024,E=256,VT=16000,G3=3072
constexpr long O_ENCGI = 0;                      // 3200x3072 row=t*64+b
constexpr long O_DEMB  = O_ENCGI + 9830400L;     // 3136x3072 row=t*64+b
constexpr long O_PART  = O_DEMB  + 9633792L;     // 4 x 64x3072 split-K partials
constexpr long O_QPART = O_PART  + 786432L;      // 4 x 64x1024
constexpr long O_HF    = O_QPART + 262144L;      // 64x1024 f32 enc h
constexpr long O_NLL   = O_HF    + 65536L;       // 3136
constexpr long SCRATCH_TOTAL = O_NLL + 3200L;

__device__ __align__(16) float g_scratch[SCRATCH_TOTAL];
__device__ int g_didx[3136];
__device__ int g_eidx[3200];

__device__ __align__(16) __nv_bfloat16 g_fcWb[16384000];
__device__ __align__(16) __nv_bfloat16 g_encWhb[3145728];
__device__ __align__(16) __nv_bfloat16 g_W1b[1048576];
__device__ __align__(16) __nv_bfloat16 g_decWxb[3145728];
__device__ __align__(16) __nv_bfloat16 g_decWxb2[786432];
__device__ __align__(16) __nv_bfloat16 g_encWxb[786432];
__device__ __align__(16) __nv_bfloat16 g_W2b[1048576];
__device__ __align__(16) __nv_bfloat16 g_encEmbb[3072000];
__device__ __align__(16) __nv_bfloat16 g_decEmbb[4096000];
__device__ __align__(16) __nv_bfloat16 g_hb[65536];       // recurrent state (enc then dec)
__device__ __align__(16) __nv_bfloat16 g_ctxb[65536];
__device__ __align__(16) __nv_bfloat16 g_eob[3276800];    // row=b*50+t
__device__ __align__(16) __nv_bfloat16 g_keysb[3276800];  // row=b*50+t
__device__ __align__(16) __nv_bfloat16 g_hallb[3211264];  // row=t*64+b
__device__ __align__(16) __nv_bfloat16 g_logitsb[50176000];

__global__ void setup_all(const int* __restrict__ inp, const int* __restrict__ targ,
                          const float* __restrict__ hsrc, float* __restrict__ hf,
                          __nv_bfloat16* __restrict__ hb){
    int i = blockIdx.x*256 + threadIdx.x;
    if (i < 65536){ float v = hsrc[i]; hf[i] = v; hb[i] = __float2bfloat16(v); }
    if (i < 3136){ int t = i >> 6, b = i & 63; g_didx[i] = targ[b*50 + t]; }
    if (i < 3200){ int t = i >> 6, b = i & 63; g_eidx[i] = inp[b*50 + t]; }
}

// ---- single merged bf16 conversion over 9 segments ----
constexpr long C1=16384000L, C2=19529728L, C3=20578304L, C4=23724032L, C5=24510464L,
               C6=25296896L, C7=26345472L, C8=29417472L, C9=33513472L;
__global__ void cvt_all(
    const float* s0, __nv_bfloat16* d0, const float* s1, __nv_bfloat16* d1,
    const float* s2, __nv_bfloat16* d2, const float* s3, __nv_bfloat16* d3,
    const float* s4, __nv_bfloat16* d4, const float* s5, __nv_bfloat16* d5,
    const float* s6, __nv_bfloat16* d6, const float* s7, __nv_bfloat16* d7,
    const float* s8, __nv_bfloat16* d8)
{
    long i = ((long)blockIdx.x*256 + threadIdx.x)*4;
    const float* src; __nv_bfloat16* dst; long off;
    if      (i < C1){ src=s0; dst=d0; off=i; }
    else if (i < C2){ src=s1; dst=d1; off=i-C1; }
    else if (i < C3){ src=s2; dst=d2; off=i-C2; }
    else if (i < C4){ src=s3; dst=d3; off=i-C3; }
    else if (i < C5){ src=s4; dst=d4; off=i-C4; }
    else if (i < C6){ src=s5; dst=d5; off=i-C5; }
    else if (i < C7){ src=s6; dst=d6; off=i-C6; }
    else if (i < C8){ src=s7; dst=d7; off=i-C7; }
    else if (i < C9){ src=s8; dst=d8; off=i-C8; }
    else return;
    float4 v = *reinterpret_cast<const float4*>(src + off);
    __nv_bfloat162 lo = __floats2bfloat162_rn(v.x, v.y);
    __nv_bfloat162 hi = __floats2bfloat162_rn(v.z, v.w);
    uint2 o; o.x = *reinterpret_cast<unsigned*>(&lo); o.y = *reinterpret_cast<unsigned*>(&hi);
    *reinterpret_cast<uint2*>(dst + off) = o;
}

// ---- general 64x64 mma GEMM, gather A, f32 and/or bf16 out (R6-proven) ----
__global__ __launch_bounds__(256) void gemm_mma(
    const __nv_bfloat16* __restrict__ A, int lda, const int* __restrict__ gidx,
    const __nv_bfloat16* __restrict__ Bm, int ldb, const float* __restrict__ bias,
    float* __restrict__ C, __nv_bfloat16* __restrict__ Cb, int ldc, int K)
{
    __shared__ __align__(16) char smA[2][8192];
    __shared__ __align__(16) char smB[2][8192];
    const int tid = threadIdx.x, warp = tid >> 5, lane = tid & 31;
    const int wm = warp >> 2, wn = warp & 3;
    const int row0 = blockIdx.y << 6, col0 = blockIdx.x << 6;
    unsigned sA[2] = { (unsigned)__cvta_generic_to_shared(smA[0]), (unsigned)__cvta_generic_to_shared(smA[1]) };
    unsigned sB[2] = { (unsigned)__cvta_generic_to_shared(smB[0]), (unsigned)__cvta_generic_to_shared(smB[1]) };
    float acc[2][2][4] = {};
    const int lr = tid >> 3, lc = tid & 7;
    long ar0 = gidx ? (long)gidx[row0+lr]*lda    : (long)(row0+lr)*lda;
    long ar1 = gidx ? (long)gidx[row0+lr+32]*lda : (long)(row0+lr+32)*lda;
    auto issue = [&](int st, int k0){
        asm volatile("cp.async.cg.shared.global [%0], [%1], 16;"
            :: "r"(sA[st] + swz(lr*128 + lc*16)), "l"(A + ar0 + k0 + lc*8));
        asm volatile("cp.async.cg.shared.global [%0], [%1], 16;"
            :: "r"(sA[st] + swz((lr+32)*128 + lc*16)), "l"(A + ar1 + k0 + lc*8));
        #pragma unroll
        for (int i=0;i<2;i++){
            int r = lr + i*32;
            asm volatile("cp.async.cg.shared.global [%0], [%1], 16;"
                :: "r"(sB[st] + swz(r*128 + lc*16)), "l"(Bm + (long)(k0+r)*ldb + col0 + lc*8));
        }
        asm volatile("cp.async.commit_group;");
    };
    const int nk = K >> 6;
    issue(0, 0);
    for (int kt = 0; kt < nk; kt++){
        if (kt + 1 < nk){ issue((kt+1)&1, (kt+1)<<6); asm volatile("cp.async.wait_group 1;" ::: "memory"); }
        else asm volatile("cp.async.wait_group 0;" ::: "memory");
        __syncthreads();
        const int st = kt & 1;
        #pragma unroll
        for (int ks = 0; ks < 4; ks++){
            unsigned a[2][4];
            #pragma unroll
            for (int mt = 0; mt < 2; mt++){
                int r = wm*32 + mt*16 + (lane & 15), c = ks*16 + (lane >> 4)*8;
                asm volatile("ldmatrix.sync.aligned.m8n8.x4.shared.b16 {%0,%1,%2,%3}, [%4];"
                    : "=r"(a[mt][0]),"=r"(a[mt][1]),"=r"(a[mt][2]),"=r"(a[mt][3])
                    : "r"(sA[st] + swz(r*128 + c*2)));
            }
            unsigned b[4];
            int kk = ks*16 + ((lane>>3)&1)*8 + (lane & 7), nn = wn*16 + (lane>>4)*8;
            asm volatile("ldmatrix.sync.aligned.m8n8.x4.trans.shared.b16 {%0,%1,%2,%3}, [%4];"
                : "=r"(b[0]),"=r"(b[1]),"=r"(b[2]),"=r"(b[3])
                : "r"(sB[st] + swz(kk*128 + nn*2)));
            #pragma unroll
            for (int mt = 0; mt < 2; mt++)
                #pragma unroll
                for (int nt = 0; nt < 2; nt++){
                    float* d = acc[mt][nt];
                    asm volatile("mma.sync.aligned.m16n8k16.row.col.f32.bf16.bf16.f32 "
                        "{%0,%1,%2,%3}, {%4,%5,%6,%7}, {%8,%9}, {%0,%1,%2,%3};"
                        : "+f"(d[0]),"+f"(d[1]),"+f"(d[2]),"+f"(d[3])
                        : "r"(a[mt][0]),"r"(a[mt][1]),"r"(a[mt][2]),"r"(a[mt][3]),
                          "r"(b[nt*2]),"r"(b[nt*2+1]));
                }
        }
        __syncthreads();
    }
    const int rb = row0 + wm*32 + (lane>>2), cb = col0 + wn*16 + (lane&3)*2;
    #pragma unroll
    for (int nt = 0; nt < 2; nt++){
        int cc = cb + nt*8;
        float bv0 = bias ? bias[cc] : 0.f, bv1 = bias ? bias[cc+1] : 0.f;
        #pragma unroll
        for (int mt = 0; mt < 2; mt++){
            int r = rb + mt*16;
            float x0 = acc[mt][nt][0]+bv0, x1 = acc[mt][nt][1]+bv1;
            float y0 = acc[mt][nt][2]+bv0, y1 = acc[mt][nt][3]+bv1;
            if (C){
                *reinterpret_cast<float2*>(&C[(long)r*ldc + cc]) = make_float2(x0, x1);
                *reinterpret_cast<float2*>(&C[(long)(r+8)*ldc + cc]) = make_float2(y0, y1);
            }
            if (Cb){
                *reinterpret_cast<__nv_bfloat162*>(&Cb[(long)r*ldc + cc]) = __floats2bfloat162_rn(x0, x1);
                *reinterpret_cast<__nv_bfloat162*>(&Cb[(long)(r+8)*ldc + cc]) = __floats2bfloat162_rn(y0, y1);
            }
        }
    }
}

// ---- split-K skinny GEMM: M=64 fixed, grid (N/64, KS); partial z -> C + z*64*N ----
__global__ __launch_bounds__(256) void gemm_splitk(
    const __nv_bfloat16* __restrict__ A, int lda,
    const __nv_bfloat16* __restrict__ Bm, int ldb,
    float* __restrict__ C, int N, int K, int KS)
{
    __shared__ __align__(16) char smA[2][8192];
    __shared__ __align__(16) char smB[2][8192];
    const int tid = threadIdx.x, warp = tid >> 5, lane = tid & 31;
    const int wm = warp >> 2, wn = warp & 3;
    const int col0 = blockIdx.x << 6;
    const int kbeg = blockIdx.y * (K / KS);
    unsigned sA[2] = { (unsigned)__cvta_generic_to_shared(smA[0]), (unsigned)__cvta_generic_to_shared(smA[1]) };
    unsigned sB[2] = { (unsigned)__cvta_generic_to_shared(smB[0]), (unsigned)__cvta_generic_to_shared(smB[1]) };
    float acc[2][2][4] = {};
    const int lr = tid >> 3, lc = tid & 7;
    auto issue = [&](int st, int k0){
        asm volatile("cp.async.cg.shared.global [%0], [%1], 16;"
            :: "r"(sA[st] + swz(lr*128 + lc*16)), "l"(A + (long)lr*lda + kbeg + k0 + lc*8));
        asm volatile("cp.async.cg.shared.global [%0], [%1], 16;"
            :: "r"(sA[st] + swz((lr+32)*128 + lc*16)), "l"(A + (long)(lr+32)*lda + kbeg + k0 + lc*8));
        #pragma unroll
        for (int i=0;i<2;i++){
            int r = lr + i*32;
            asm volatile("cp.async.cg.shared.global [%0], [%1], 16;"
                :: "r"(sB[st] + swz(r*128 + lc*16)), "l"(Bm + (long)(kbeg+k0+r)*ldb + col0 + lc*8));
        }
        asm volatile("cp.async.commit_group;");
    };
    const int nk = (K / KS) >> 6;
    issue(0, 0);
    for (int kt = 0; kt < nk; kt++){
        if (kt + 1 < nk){ issue((kt+1)&1, (kt+1)<<6); asm volatile("cp.async.wait_group 1;" ::: "memory"); }
        else asm volatile("cp.async.wait_group 0;" ::: "memory");
        __syncthreads();
        const int st = kt & 1;
        #pragma unroll
        for (int ks = 0; ks < 4; ks++){
            unsigned a[2][4];
            #pragma unroll
            for (int mt = 0; mt < 2; mt++){
                int r = wm*32 + mt*16 + (lane & 15), c = ks*16 + (lane >> 4)*8;
                asm volatile("ldmatrix.sync.aligned.m8n8.x4.shared.b16 {%0,%1,%2,%3}, [%4];"
                    : "=r"(a[mt][0]),"=r"(a[mt][1]),"=r"(a[mt][2]),"=r"(a[mt][3])
                    : "r"(sA[st] + swz(r*128 + c*2)));
            }
            unsigned b[4];
            int kk = ks*16 + ((lane>>3)&1)*8 + (lane & 7), nn = wn*16 + (lane>>4)*8;
            asm volatile("ldmatrix.sync.aligned.m8n8.x4.trans.shared.b16 {%0,%1,%2,%3}, [%4];"
                : "=r"(b[0]),"=r"(b[1]),"=r"(b[2]),"=r"(b[3])
                : "r"(sB[st] + swz(kk*128 + nn*2)));
            #pragma unroll
            for (int mt = 0; mt < 2; mt++)
                #pragma unroll
                for (int nt = 0; nt < 2; nt++){
                    float* d = acc[mt][nt];
                    asm volatile("mma.sync.aligned.m16n8k16.row.col.f32.bf16.bf16.f32 "
                        "{%0,%1,%2,%3}, {%4,%5,%6,%7}, {%8,%9}, {%0,%1,%2,%3};"
                        : "+f"(d[0]),"+f"(d[1]),"+f"(d[2]),"+f"(d[3])
                        : "r"(a[mt][0]),"r"(a[mt][1]),"r"(a[mt][2]),"r"(a[mt][3]),
                          "r"(b[nt*2]),"r"(b[nt*2+1]));
                }
        }
        __syncthreads();
    }
    float* Cout = C + (long)blockIdx.y * 64 * N;
    const int rb = wm*32 + (lane>>2), cb = col0 + wn*16 + (lane&3)*2;
    #pragma unroll
    for (int nt = 0; nt < 2; nt++){
        int cc = cb + nt*8;
        #pragma unroll
        for (int mt = 0; mt < 2; mt++){
            int r = rb + mt*16;
            *reinterpret_cast<float2*>(&Cout[(long)r*N + cc]) = make_float2(acc[mt][nt][0], acc[mt][nt][1]);
            *reinterpret_cast<float2*>(&Cout[(long)(r+8)*N + cc]) = make_float2(acc[mt][nt][2], acc[mt][nt][3]);
        }
    }
}

// ---- encoder GRU combine: sum 4 partials + gates + state update ----
__global__ __launch_bounds__(256) void enc_combine(
    int t, const float* __restrict__ encgi, const float* __restrict__ part,
    const float* __restrict__ encb2,
    float* __restrict__ hf, __nv_bfloat16* __restrict__ hb, __nv_bfloat16* __restrict__ eob)
{
    const int PS = 64*3072;
    int i = blockIdx.x*256 + threadIdx.x;
    int b = i >> 10, u = i & 1023;
    long p = (long)b*3072 + u;
    long gi = (long)(t*64 + b)*3072 + u;
    float ghz = part[p]      + part[PS+p]      + part[2*PS+p]      + part[3*PS+p]      + encb2[u];
    float ghr = part[p+1024] + part[PS+p+1024] + part[2*PS+p+1024] + part[3*PS+p+1024] + encb2[1024+u];
    float ghh = part[p+2048] + part[PS+p+2048] + part[2*PS+p+2048] + part[3*PS+p+2048] + encb2[2048+u];
    float z = sigm(encgi[gi] + ghz);
    float r = sigm(encgi[gi+1024] + ghr);
    float hc = ftanh(encgi[gi+2048] + r*ghh);
    float hn = z*hf[i] + (1.0f - z)*hc;
    hf[i] = hn;
    hb[i] = __float2bfloat16(hn);
    eob[(long)(b*50 + t)*1024 + u] = __float2bfloat16(hn);
}

// ---- decoder GRU combine (h==0) ----
__global__ __launch_bounds__(256) void dec_combine(
    int t, const float* __restrict__ dembgi, const float* __restrict__ part,
    const float* __restrict__ decb2,
    __nv_bfloat16* __restrict__ hb, __nv_bfloat16* __restrict__ hallb)
{
    const int PS = 64*3072;
    int i = blockIdx.x*256 + threadIdx.x;
    int b = i >> 10, u = i & 1023;
    long p = (long)b*3072 + u;
    long gi = (long)(t*64 + b)*3072 + u;
    float gz = part[p]      + part[PS+p]      + part[2*PS+p]      + part[3*PS+p];
    float gr = part[p+1024] + part[PS+p+1024] + part[2*PS+p+1024] + part[3*PS+p+1024];
    float gh = part[p+2048] + part[PS+p+2048] + part[2*PS+p+2048] + part[3*PS+p+2048];
    float z = sigm(dembgi[gi] + gz + decb2[u]);
    float r = sigm(dembgi[gi+1024] + gr + decb2[1024+u]);
    float hc = ftanh(dembgi[gi+2048] + gh + r*decb2[2048+u]);
    float hn = (1.0f - z)*hc;
    __nv_bfloat16 hv = __float2bfloat16(hn);
    hb[i] = hv;
    hallb[(long)(t*64 + b)*1024 + u] = hv;
}

// ---- fused attention: sum 4 q-partials, scores (tanh.approx), softmax, ctx; bf16 keys/eo ----
__global__ __launch_bounds__(256) void attention(
    const float* __restrict__ qpart, const __nv_bfloat16* __restrict__ keysb,
    const __nv_bfloat16* __restrict__ eob, __nv_bfloat16* __restrict__ ctxb,
    const float* __restrict__ b1, const float* __restrict__ V, const float* __restrict__ bV)
{
    __shared__ float qs[1024];
    __shared__ float Vs[1024];
    __shared__ float sc[64];
    const int b = blockIdx.x, tid = threadIdx.x, warp = tid>>5, lane = tid&31;
    const int QP = 65536;
    for (int u = tid; u < 1024; u += 256){
        long p = b*1024 + u;
        qs[u] = qpart[p] + qpart[QP+p] + qpart[2*QP+p] + qpart[3*QP+p] + b1[u];
        Vs[u] = V[u];
    }
    __syncthreads();
    for (int s = warp; s < 50; s += 8){
        const __nv_bfloat16* kr = keysb + (long)(b*50 + s)*1024;
        float a = 0.f;
        for (int u = lane*2; u < 1024; u += 64){
            __nv_bfloat162 k2 = *reinterpret_cast<const __nv_bfloat162*>(kr + u);
            a += Vs[u]   * tanha(qs[u]   + __bfloat162float(k2.x));
            a += Vs[u+1] * tanha(qs[u+1] + __bfloat162float(k2.y));
        }
        #pragma unroll
        for (int o = 16; o; o >>= 1) a += __shfl_xor_sync(0xffffffffu, a, o);
        if (lane == 0) sc[s] = a + bV[0];
    }
    __syncthreads();
    if (warp == 0){
        float v0 = sc[lane];
        bool has1 = (lane + 32) < 50;
        float v1 = has1 ? sc[lane + 32] : -1e30f;
        float m = fmaxf(v0, v1);
        #pragma unroll
        for (int o = 16; o; o >>= 1) m = fmaxf(m, __shfl_xor_sync(0xffffffffu, m, o));
        float e0 = __expf(v0 - m);
        float e1 = has1 ? __expf(v1 - m) : 0.f;
        float ssum = e0 + e1;
        #pragma unroll
        for (int o = 16; o; o >>= 1) ssum += __shfl_xor_sync(0xffffffffu, ssum, o);
        float inv = 1.0f / ssum;
        sc[lane] = e0 * inv;
        sc[lane + 32] = e1 * inv;
    }
    __syncthreads();
    for (int u0 = tid*2; u0 < 1024; u0 += 512){
        float a0 = 0.f, a1 = 0.f;
        const __nv_bfloat16* er = eob + (long)b*51200 + u0;
        #pragma unroll 10
        for (int s = 0; s < 50; s++){
            __nv_bfloat162 e2 = *reinterpret_cast<const __nv_bfloat162*>(er + (long)s*1024);
            a0 = fmaf(sc[s], __bfloat162float(e2.x), a0);
            a1 = fmaf(sc[s], __bfloat162float(e2.y), a1);
        }
        *reinterpret_cast<__nv_bfloat162*>(&ctxb[b*1024 + u0]) = __floats2bfloat162_rn(a0, a1);
    }
}

// ---- fc GEMM: BM=128 BN=128 BK=64, bf16 out (verified bit-exact) ----
__global__ __launch_bounds__(256) void gemm_fc(
    const __nv_bfloat16* __restrict__ A, const __nv_bfloat16* __restrict__ Bm,
    const float* __restrict__ bias, __nv_bfloat16* __restrict__ Cb)
{
    extern __shared__ char sm[];
    const int tid = threadIdx.x, warp = tid >> 5, lane = tid & 31;
    const int wm = warp >> 2, wn = warp & 3;
    const int row0 = blockIdx.y << 7, col0 = blockIdx.x << 7;
    unsigned base = (unsigned)__cvta_generic_to_shared(sm);
    float acc[4][4][4] = {};
    auto issue = [&](int st, int k0){
        unsigned sA = base + st*32768, sB = sA + 16384;
        int r = tid>>3, c8 = tid&7;
        #pragma unroll
        for (int i=0;i<4;i++){
            int rr = r + i*32;
            int rg = row0 + rr; if (rg > 3135) rg = 3135;
            asm volatile("cp.async.cg.shared.global [%0], [%1], 16;"
                :: "r"(sA + swz(rr*128 + c8*16)), "l"(A + (long)rg*1024 + k0 + c8*8));
        }
        #pragma unroll
        for (int p=0;p<4;p++){
            int idx = p*256 + tid;
            int rr = idx>>4, c16 = idx&15;
            int panel = c16>>3, cp = c16&7;
            asm volatile("cp.async.cg.shared.global [%0], [%1], 16;"
                :: "r"(sB + panel*8192 + swz(rr*128 + cp*16)),
                   "l"(Bm + (long)(k0+rr)*16000 + col0 + c16*8));
        }
        asm volatile("cp.async.commit_group;");
    };
    issue(0, 0);
    for (int kt = 0; kt < 16; kt++){
        if (kt+1 < 16){ issue((kt+1)&1, (kt+1)<<6); asm volatile("cp.async.wait_group 1;" ::: "memory"); }
        else asm volatile("cp.async.wait_group 0;" ::: "memory");
        __syncthreads();
        unsigned sA = base + (kt&1)*32768, sB = sA + 16384;
        #pragma unroll
        for (int ks = 0; ks < 4; ks++){
            unsigned a[4][4];
            #pragma unroll
            for (int mt = 0; mt < 4; mt++){
                int r = wm*64 + mt*16 + (lane & 15), c = ks*16 + (lane >> 4)*8;
                asm volatile("ldmatrix.sync.aligned.m8n8.x4.shared.b16 {%0,%1,%2,%3}, [%4];"
                    : "=r"(a[mt][0]),"=r"(a[mt][1]),"=r"(a[mt][2]),"=r"(a[mt][3])
                    : "r"(sA + swz(r*128 + c*2)));
            }
            #pragma unroll
            for (int nt = 0; nt < 4; nt++){
                int nb = wn*4 + nt;
                int panel = nb>>3, cip = nb&7;
                unsigned b2[2];
                int kk = ks*16 + (lane & 15);
                asm volatile("ldmatrix.sync.aligned.m8n8.x2.trans.shared.b16 {%0,%1}, [%2];"
                    : "=r"(b2[0]),"=r"(b2[1])
                    : "r"(sB + panel*8192 + swz(kk*128 + cip*16)));
                #pragma unroll
                for (int mt = 0; mt < 4; mt++){
                    float* d = acc[mt][nt];
                    asm volatile("mma.sync.aligned.m16n8k16.row.col.f32.bf16.bf16.f32 "
                        "{%0,%1,%2,%3}, {%4,%5,%6,%7}, {%8,%9}, {%0,%1,%2,%3};"
                        : "+f"(d[0]),"+f"(d[1]),"+f"(d[2]),"+f"(d[3])
                        : "r"(a[mt][0]),"r"(a[mt][1]),"r"(a[mt][2]),"r"(a[mt][3]),
                          "r"(b2[0]),"r"(b2[1]));
                }
            }
        }
        __syncthreads();
    }
    #pragma unroll
    for (int nt = 0; nt < 4; nt++){
        int c = col0 + wn*32 + nt*8 + (lane&3)*2;
        float bv0 = bias[c], bv1 = bias[c+1];
        #pragma unroll
        for (int mt = 0; mt < 4; mt++){
            int r = row0 + wm*64 + mt*16 + (lane>>2);
            if (r < 3136)
                *reinterpret_cast<__nv_bfloat162*>(&Cb[(long)r*16000 + c]) =
                    __floats2bfloat162_rn(acc[mt][nt][0]+bv0, acc[mt][nt][1]+bv1);
            if (r+8 < 3136)
                *reinterpret_cast<__nv_bfloat162*>(&Cb[(long)(r+8)*16000 + c]) =
                    __floats2bfloat162_rn(acc[mt][nt][2]+bv0, acc[mt][nt][3]+bv1);
        }
    }
}

// ---- loss over bf16 logits ----
__global__ __launch_bounds__(256) void loss_kernel(
    const __nv_bfloat16* __restrict__ lg, const int* __restrict__ targ, float* __restrict__ nll)
{
    __shared__ float red[256];
    const int row = blockIdx.x, tid = threadIdx.x;
    const int t = row >> 6, b = row & 63;
    const __nv_bfloat16* lr = lg + (long)row*16000;
    float m = -1e30f;
    for (int j = tid*2; j < 16000; j += 512){
        __nv_bfloat162 p = *reinterpret_cast<const __nv_bfloat162*>(lr + j);
        m = fmaxf(m, fmaxf(__bfloat162float(p.x), __bfloat162float(p.y)));
    }
    red[tid] = m; __syncthreads();
    for (int o = 128; o; o >>= 1){ if (tid < o) red[tid] = fmaxf(red[tid], red[tid+o]); __syncthreads(); }
    m = red[0]; __syncthreads();
    float s = 0.f;
    for (int j = tid*2; j < 16000; j += 512){
        __nv_bfloat162 p = *reinterpret_cast<const __nv_bfloat162*>(lr + j);
        s += __expf(__bfloat162float(p.x) - m) + __expf(__bfloat162float(p.y) - m);
    }
    red[tid] = s; __syncthreads();
    for (int o = 128; o; o >>= 1){ if (tid < o) red[tid] += red[tid+o]; __syncthreads(); }
    if (tid == 0){
        int yt = targ[b*50 + t + 1];
        float lse = m + __logf(red[0]);
        nll[row] = (yt != 0) ? (lse - __bfloat162float(lr[yt])) * (1.0f/64.0f) : 0.f;
    }
}
__global__ __launch_bounds__(1024) void final_reduce(const float* __restrict__ nll, float* __restrict__ out){
    __shared__ float red[1024];
    int tid = threadIdx.x;
    float s = 0.f;
    for (int i = tid; i < 3136; i += 1024) s += nll[i];
    red[tid] = s; __syncthreads();
    for (int o = 512; o; o >>= 1){ if (tid < o) red[tid] += red[tid+o]; __syncthreads(); }
    if (tid == 0) out[0] = red[0];
}

extern "C" void kernel_launch(void* const* d_in, const int* in_sizes, int n_in,
                              void* d_out, int out_size) {
    const int*   inp     = (const int*)  d_in[0];
    const int*   targ    = (const int*)  d_in[1];
    const float* enc_hid = (const float*)d_in[2];
    const float* enc_emb = (const float*)d_in[3];
    const float* enc_Wx  = (const float*)d_in[4];
    const float* enc_Wh  = (const float*)d_in[5];
    const float* enc_b   = (const float*)d_in[6];
    const float* W1      = (const float*)d_in[7];
    const float* b1      = (const float*)d_in[8];
    const float* W2      = (const float*)d_in[9];
    const float* b2      = (const float*)d_in[10];
    const float* V       = (const float*)d_in[11];
    const float* bV      = (const float*)d_in[12];
    const float* dec_emb = (const float*)d_in[13];
    const float* dec_Wx  = (const float*)d_in[14];
    const float* dec_b   = (const float*)d_in[16];
    const float* fc_W    = (const float*)d_in[17];
    const float* fc_b    = (const float*)d_in[18];
    float* out = (float*)d_out;

    float* S; cudaGetSymbolAddress((void**)&S, g_scratch);
    int *didx, *eidx;
    cudaGetSymbolAddress((void**)&didx, g_didx);
    cudaGetSymbolAddress((void**)&eidx, g_eidx);
    __nv_bfloat16 *fcWb,*encWhb,*W1b,*decWxb,*decWxb2,*encWxb,*W2b,*encEmbb,*decEmbb;
    __nv_bfloat16 *hb,*ctxb,*eob,*keysb,*hallb,*logitsb;
    cudaGetSymbolAddress((void**)&fcWb,    g_fcWb);
    cudaGetSymbolAddress((void**)&encWhb,  g_encWhb);
    cudaGetSymbolAddress((void**)&W1b,     g_W1b);
    cudaGetSymbolAddress((void**)&decWxb,  g_decWxb);
    cudaGetSymbolAddress((void**)&decWxb2, g_decWxb2);
    cudaGetSymbolAddress((void**)&encWxb,  g_encWxb);
    cudaGetSymbolAddress((void**)&W2b,     g_W2b);
    cudaGetSymbolAddress((void**)&encEmbb, g_encEmbb);
    cudaGetSymbolAddress((void**)&decEmbb, g_decEmbb);
    cudaGetSymbolAddress((void**)&hb,      g_hb);
    cudaGetSymbolAddress((void**)&ctxb,    g_ctxb);
    cudaGetSymbolAddress((void**)&eob,     g_eob);
    cudaGetSymbolAddress((void**)&keysb,   g_keysb);
    cudaGetSymbolAddress((void**)&hallb,   g_hallb);
    cudaGetSymbolAddress((void**)&logitsb, g_logitsb);

    float* encgi = S + O_ENCGI;
    float* dembgi= S + O_DEMB;
    float* part  = S + O_PART;
    float* qpart = S + O_QPART;
    float* hf    = S + O_HF;
    float* nll   = S + O_NLL;

    cudaFuncSetAttribute(gemm_fc, cudaFuncAttributeMaxDynamicSharedMemorySize, 65536);

    setup_all<<<256, 256>>>(inp, targ, enc_hid, hf, hb);

    // all weight/embedding conversions in ONE node
    cvt_all<<<32728, 256>>>(
        fc_W, fcWb, enc_Wh, encWhb, W1, W1b, dec_Wx, decWxb,
        dec_Wx + 1024L*3072, decWxb2, enc_Wx, encWxb, W2, W2b,
        enc_emb, encEmbb, dec_emb, decEmbb);

    // hoisted input-side GEMMs
    gemm_mma<<<dim3(48, 50), 256>>>(encEmbb, 256, eidx, encWxb,  3072, enc_b, encgi,  nullptr, 3072, 256);
    gemm_mma<<<dim3(48, 49), 256>>>(decEmbb, 256, didx, decWxb2, 3072, dec_b, dembgi, nullptr, 3072, 256);

    // encoder: split-K gemm (192 blocks) + combine, per step
    for (int t = 0; t < 50; t++){
        gemm_splitk<<<dim3(48, 4), 256>>>(hb, 1024, encWhb, 3072, part, 3072, 1024, 4);
        enc_combine<<<256, 256>>>(t, encgi, part, enc_b + 3072, hf, hb, eob);
    }

    // keys = enc_out @ W2 + b2 (bf16 out, row = b*50+t)
    gemm_mma<<<dim3(16, 50), 256>>>(eob, 1024, nullptr, W2b, 1024, b2, nullptr, keysb, 1024, 1024);

    // decoder: q split-K + fused attention + gates split-K + combine
    for (int t = 0; t < 49; t++){
        gemm_splitk<<<dim3(16, 4), 256>>>(hb, 1024, W1b, 1024, qpart, 1024, 1024, 4);
        attention<<<64, 256>>>(qpart, keysb, eob, ctxb, b1, V, bV);
        gemm_splitk<<<dim3(48, 4), 256>>>(ctxb, 1024, decWxb, 3072, part, 3072, 1024, 4);
        dec_combine<<<256, 256>>>(t, dembgi, part, dec_b + 3072, hb, hallb);
    }

    // batched fc logits, 128x128 tiles (bf16 out)
    gemm_fc<<<dim3(125, 25), 256, 65536>>>(hallb, fcWb, fc_b, logitsb);

    loss_kernel<<<3136, 256>>>(logitsb, targ, nll);
    final_reduce<<<1, 1024>>>(nll, out);
}